// round 2
// baseline (speedup 1.0000x reference)
#include <cuda_runtime.h>
#include <cuda_bf16.h>
#include <math.h>

// ---------------------------------------------------------------------------
// DeepSetEncoder: x[64,512,512] -> phi MLP (512->1024->1024, relu) ->
// sum+max pool over N=512 -> concat [64,2048] -> rho MLP (2048->1024->1024).
// Round 1: fp32 SGEMM baseline; pooling fused into GEMM2 epilogue
// (atomicAdd for sum, bit-trick atomicMax for max of nonneg values).
// ---------------------------------------------------------------------------

#define B_SZ   64
#define N_SET  512
#define D_IN   512
#define D_H    1024
#define M_BIG  (B_SZ * N_SET)   // 32768

// Scratch (device globals: allocation-free per harness rules)
__device__ float g_h1[(size_t)M_BIG * D_H];      // 128 MB
__device__ float g_pooled[B_SZ * 2 * D_H];       // [64, 2048]
__device__ float g_r1[B_SZ * D_H];               // [64, 1024]

#define BM 128
#define BN 128
#define BK 8
#define TM 8
#define TN 8

// C[M,N] = relu(A[M,K] @ W[K,N] + bias[N])
// If POOL: instead of storing C, reduce the 128-row tile (one batch element)
// into pooled[b, 0:N] (sum) and pooled[b, N:2N] (max) via atomics.
template <bool POOL>
__global__ __launch_bounds__(256, 2) void sgemm_bias_relu(
    const float* __restrict__ A, const float* __restrict__ W,
    const float* __restrict__ bias, float* __restrict__ C,
    float* __restrict__ pooled,
    int M, int N, int K)
{
    __shared__ float As[2][BK][BM];
    __shared__ float Bs[2][BK][BN];

    const int tid = threadIdx.x;
    const int tx  = tid & 15;        // 0..15 -> N direction
    const int ty  = tid >> 4;        // 0..15 -> M direction
    const int bm0 = blockIdx.y * BM;
    const int bn0 = blockIdx.x * BN;

    // Global->smem load mapping
    const int arow = tid >> 1;          // 0..127
    const int acol = (tid & 1) * 4;     // 0 or 4
    const int brow = tid >> 5;          // 0..7
    const int bcol = (tid & 31) * 4;    // 0..124

    const int agrow   = bm0 + arow;
    const bool avalid = (agrow < M);
    const float* Aptr = A + (size_t)agrow * K + acol;
    const float* Wptr = W + (size_t)brow * N + bn0 + bcol;

    float acc[TM][TN];
    #pragma unroll
    for (int i = 0; i < TM; i++)
        #pragma unroll
        for (int j = 0; j < TN; j++)
            acc[i][j] = 0.0f;

    // ---- stage tile 0 ----
    float4 pa, pb;
    pa = avalid ? *(const float4*)(Aptr) : make_float4(0.f, 0.f, 0.f, 0.f);
    pb = *(const float4*)(Wptr);
    As[0][acol + 0][arow] = pa.x;
    As[0][acol + 1][arow] = pa.y;
    As[0][acol + 2][arow] = pa.z;
    As[0][acol + 3][arow] = pa.w;
    *(float4*)&Bs[0][brow][bcol] = pb;
    __syncthreads();

    const int kt = K / BK;
    int buf = 0;

    for (int t = 0; t < kt; t++) {
        // prefetch next tile into registers
        if (t + 1 < kt) {
            const int k0 = (t + 1) * BK;
            pa = avalid ? *(const float4*)(Aptr + k0) : make_float4(0.f, 0.f, 0.f, 0.f);
            pb = *(const float4*)(Wptr + (size_t)k0 * N);
        }

        // compute on current buffer
        #pragma unroll
        for (int k = 0; k < BK; k++) {
            float ra[TM], rb[TN];
            *(float4*)&ra[0] = *(const float4*)&As[buf][k][ty * TM];
            *(float4*)&ra[4] = *(const float4*)&As[buf][k][ty * TM + 4];
            *(float4*)&rb[0] = *(const float4*)&Bs[buf][k][tx * TN];
            *(float4*)&rb[4] = *(const float4*)&Bs[buf][k][tx * TN + 4];
            #pragma unroll
            for (int i = 0; i < TM; i++)
                #pragma unroll
                for (int j = 0; j < TN; j++)
                    acc[i][j] = fmaf(ra[i], rb[j], acc[i][j]);
        }

        // commit prefetched tile to the other buffer
        if (t + 1 < kt) {
            const int nb = buf ^ 1;
            As[nb][acol + 0][arow] = pa.x;
            As[nb][acol + 1][arow] = pa.y;
            As[nb][acol + 2][arow] = pa.z;
            As[nb][acol + 3][arow] = pa.w;
            *(float4*)&Bs[nb][brow][bcol] = pb;
            __syncthreads();
            buf = nb;
        }
    }

    // ---- epilogue ----
    float bv[TN];
    *(float4*)&bv[0] = *(const float4*)(bias + bn0 + tx * TN);
    *(float4*)&bv[4] = *(const float4*)(bias + bn0 + tx * TN + 4);

    if (!POOL) {
        #pragma unroll
        for (int i = 0; i < TM; i++) {
            const int grow = bm0 + ty * TM + i;
            if (grow < M) {
                float o[TN];
                #pragma unroll
                for (int j = 0; j < TN; j++)
                    o[j] = fmaxf(acc[i][j] + bv[j], 0.0f);
                float* cp = C + (size_t)grow * N + bn0 + tx * TN;
                *(float4*)(cp + 0) = *(float4*)&o[0];
                *(float4*)(cp + 4) = *(float4*)&o[4];
            }
        }
    } else {
        // Per-thread column partials over this thread's 8 rows (all in one b).
        float psum[TN], pmax[TN];
        #pragma unroll
        for (int j = 0; j < TN; j++) { psum[j] = 0.0f; pmax[j] = 0.0f; }
        #pragma unroll
        for (int i = 0; i < TM; i++) {
            #pragma unroll
            for (int j = 0; j < TN; j++) {
                const float v = fmaxf(acc[i][j] + bv[j], 0.0f);
                psum[j] += v;
                pmax[j]  = fmaxf(pmax[j], v);
            }
        }

        // Reduce across the 16 ty groups in smem (reuse As/Bs: 2x [16][128]).
        float (*redS)[BN] = (float (*)[BN])&As[0][0][0];   // 8 KB
        float (*redM)[BN] = (float (*)[BN])&Bs[0][0][0];   // 8 KB
        __syncthreads();   // done with mainloop smem
        #pragma unroll
        for (int j = 0; j < TN; j++) {
            redS[ty][tx * TN + j] = psum[j];
            redM[ty][tx * TN + j] = pmax[j];
        }
        __syncthreads();
        #pragma unroll
        for (int s = 8; s >= 1; s >>= 1) {
            if (ty < s) {
                #pragma unroll
                for (int j = 0; j < TN; j++) {
                    const int c = tx * TN + j;
                    redS[ty][c] += redS[ty + s][c];
                    redM[ty][c]  = fmaxf(redM[ty][c], redM[ty + s][c]);
                }
            }
            __syncthreads();
        }
        if (ty == 0) {
            const int b = bm0 / N_SET;   // 128-row tile lies within one batch elem
            #pragma unroll
            for (int j = 0; j < TN; j++) {
                const int c = bn0 + tx * TN + j;
                atomicAdd(&pooled[b * (2 * D_H) + c], redS[0][tx * TN + j]);
                // values >= 0: integer bit compare == float compare
                atomicMax((int*)&pooled[b * (2 * D_H) + D_H + c],
                          __float_as_int(redM[0][tx * TN + j]));
            }
        }
    }
}

__global__ void zero_pooled(float* __restrict__ pooled)
{
    const int i = blockIdx.x * blockDim.x + threadIdx.x;
    if (i < B_SZ * 2 * D_H) pooled[i] = 0.0f;
}

extern "C" void kernel_launch(void* const* d_in, const int* in_sizes, int n_in,
                              void* d_out, int out_size)
{
    const float* x      = (const float*)d_in[0];
    const float* W_phi1 = (const float*)d_in[1];
    const float* b_phi1 = (const float*)d_in[2];
    const float* W_phi2 = (const float*)d_in[3];
    const float* b_phi2 = (const float*)d_in[4];
    const float* W_rho1 = (const float*)d_in[5];
    const float* b_rho1 = (const float*)d_in[6];
    const float* W_rho2 = (const float*)d_in[7];
    const float* b_rho2 = (const float*)d_in[8];
    float* out = (float*)d_out;

    float *h1, *pooled, *r1;
    cudaGetSymbolAddress((void**)&h1, g_h1);
    cudaGetSymbolAddress((void**)&pooled, g_pooled);
    cudaGetSymbolAddress((void**)&r1, g_r1);

    // pooled accumulators start at 0 (valid for sum, and for max of relu>=0)
    zero_pooled<<<(B_SZ * 2 * D_H + 255) / 256, 256>>>(pooled);

    // phi layer 1: [32768, 512] @ [512, 1024] -> h1
    {
        dim3 grid(D_H / BN, M_BIG / BM);
        sgemm_bias_relu<false><<<grid, 256>>>(x, W_phi1, b_phi1, h1, nullptr,
                                              M_BIG, D_H, D_IN);
    }
    // phi layer 2 + fused pooling: [32768, 1024] @ [1024, 1024] -> pooled
    {
        dim3 grid(D_H / BN, M_BIG / BM);
        sgemm_bias_relu<true><<<grid, 256>>>(h1, W_phi2, b_phi2, nullptr, pooled,
                                             M_BIG, D_H, D_H);
    }
    // rho layer 1: [64, 2048] @ [2048, 1024] -> r1
    {
        dim3 grid(D_H / BN, (B_SZ + BM - 1) / BM);
        sgemm_bias_relu<false><<<grid, 256>>>(pooled, W_rho1, b_rho1, r1, nullptr,
                                              B_SZ, D_H, 2 * D_H);
    }
    // rho layer 2: [64, 1024] @ [1024, 1024] -> output
    {
        dim3 grid(D_H / BN, (B_SZ + BM - 1) / BM);
        sgemm_bias_relu<false><<<grid, 256>>>(r1, W_rho2, b_rho2, out, nullptr,
                                              B_SZ, D_H, D_H);
    }
}

// round 8
// speedup vs baseline: 2.8397x; 2.8397x over previous
#include <cuda_runtime.h>
#include <cuda_bf16.h>
#include <math.h>
#include <stdint.h>

// ---------------------------------------------------------------------------
// DeepSetEncoder — Round 8: mma.sync bf16 (3-term hi/lo split) GEMMs.
// Fix vs R7: rho_splitk shared array Ws stride 65 -> 68 floats. The float4
// stores *(float4*)&Ws[kk][seg*8] were 16B-misaligned for odd kk (65*4=260B
// row stride) -> "misaligned address" trap. 68*4=272B is 16B-aligned.
// ---------------------------------------------------------------------------

#define B_SZ   64
#define N_SET  512
#define D_IN   512
#define D_H    1024
#define M_BIG  (B_SZ * N_SET)   // 32768

// ---- device scratch (256B-aligned) ----
__device__ __align__(256) __nv_bfloat16 g_xh[(size_t)M_BIG * D_IN];
__device__ __align__(256) __nv_bfloat16 g_xl[(size_t)M_BIG * D_IN];
__device__ __align__(256) __nv_bfloat16 g_h1h[(size_t)M_BIG * D_H];
__device__ __align__(256) __nv_bfloat16 g_h1l[(size_t)M_BIG * D_H];
__device__ __align__(256) __nv_bfloat16 g_wt1h[D_H * D_IN];
__device__ __align__(256) __nv_bfloat16 g_wt1l[D_H * D_IN];
__device__ __align__(256) __nv_bfloat16 g_wt2h[D_H * D_H];
__device__ __align__(256) __nv_bfloat16 g_wt2l[D_H * D_H];
__device__ __align__(256) float g_pooled[B_SZ * 2 * D_H];
__device__ __align__(256) float g_racc1[B_SZ * D_H];
__device__ __align__(256) float g_r1[B_SZ * D_H];
__device__ __align__(256) float g_racc2[B_SZ * D_H];

// ---- helpers ----
__device__ __forceinline__ uint32_t smem_u32(const void* p) {
    uint32_t a;
    asm("{ .reg .u64 t; cvta.to.shared.u64 t, %1; cvt.u32.u64 %0, t; }"
        : "=r"(a) : "l"(p));
    return a;
}
#define SWZ(o) ((o) ^ (((o) >> 3) & 0x70))

__device__ __forceinline__ void cp16(uint32_t dst, const void* src) {
    asm volatile("cp.async.cg.shared.global [%0], [%1], 16;" :: "r"(dst), "l"(src));
}
#define CP_COMMIT() asm volatile("cp.async.commit_group;" ::: "memory")
#define CP_WAIT0()  asm volatile("cp.async.wait_group 0;" ::: "memory")

__device__ __forceinline__ void ldsm4(uint32_t& r0, uint32_t& r1, uint32_t& r2, uint32_t& r3,
                                      uint32_t addr) {
    asm volatile("ldmatrix.sync.aligned.m8n8.x4.shared.b16 {%0,%1,%2,%3}, [%4];"
                 : "=r"(r0), "=r"(r1), "=r"(r2), "=r"(r3) : "r"(addr));
}
__device__ __forceinline__ void mma16816(float* c, uint32_t a0, uint32_t a1, uint32_t a2,
                                         uint32_t a3, uint32_t b0, uint32_t b1) {
    asm volatile(
        "mma.sync.aligned.m16n8k16.row.col.f32.bf16.bf16.f32 "
        "{%0,%1,%2,%3}, {%4,%5,%6,%7}, {%8,%9}, {%0,%1,%2,%3};"
        : "+f"(c[0]), "+f"(c[1]), "+f"(c[2]), "+f"(c[3])
        : "r"(a0), "r"(a1), "r"(a2), "r"(a3), "r"(b0), "r"(b1));
}

__device__ __forceinline__ void split_pack(float a, float b, uint32_t& hi, uint32_t& lo) {
    __nv_bfloat16 ah = __float2bfloat16_rn(a);
    __nv_bfloat16 al = __float2bfloat16_rn(a - __bfloat162float(ah));
    __nv_bfloat16 bh = __float2bfloat16_rn(b);
    __nv_bfloat16 bl = __float2bfloat16_rn(b - __bfloat162float(bh));
    hi = (uint32_t)*(uint16_t*)&ah | ((uint32_t)*(uint16_t*)&bh << 16);
    lo = (uint32_t)*(uint16_t*)&al | ((uint32_t)*(uint16_t*)&bl << 16);
}

// ---- smem layout (dynamic): 4 x 16KB A bufs, 4 x 16KB B bufs, misc ----
#define ABUF(sb, buf, t) ((sb) + ((buf) * 2 + (t)) * 16384)
#define BBUF(sb, buf, t) ((sb) + 65536 + ((buf) * 2 + (t)) * 16384)
#define SM_PSUM    102400
#define SM_PMAX    104448
#define SM_BIAS    131072
#define SMEM_DYN   (131072 + 512)
#define STG_STRIDE 132

// fill one K-chunk: A[128x64] hi/lo + B[128x64] hi/lo via cp.async
// 2 threads per row; each thread 4x16B per array.
__device__ __forceinline__ void fill_chunk(uint32_t sb, int buf, int kc,
    const __nv_bfloat16* __restrict__ Ah, const __nv_bfloat16* __restrict__ Al,
    const __nv_bfloat16* __restrict__ Bh, const __nv_bfloat16* __restrict__ Bl,
    int bm0, int bn0, int K, int tid)
{
    const int r = tid >> 1, h = tid & 1;
    const uint32_t base = (uint32_t)(r * 128 + h * 64);
    const uint32_t aHi = ABUF(sb, buf, 0), aLo = ABUF(sb, buf, 1);
    const uint32_t bHi = BBUF(sb, buf, 0), bLo = BBUF(sb, buf, 1);
    const size_t aoff = (size_t)(bm0 + r) * K + kc * 64 + h * 32;
    const size_t boff = (size_t)(bn0 + r) * K + kc * 64 + h * 32;
    #pragma unroll
    for (int i = 0; i < 4; i++) {
        const uint32_t off = SWZ(base + i * 16);
        cp16(aHi + off, Ah + aoff + i * 8);
        cp16(aLo + off, Al + aoff + i * 8);
        cp16(bHi + off, Bh + boff + i * 8);
        cp16(bLo + off, Bl + boff + i * 8);
    }
}

// ---- bf16 3-term tensor-core GEMM: C = relu(A @ B^T + bias) ----
// POOL=0: write hi/lo bf16 pair. POOL=1: fused sum/max pooling.
template <int POOL>
__global__ __launch_bounds__(256, 1) void gemm_mma(
    const __nv_bfloat16* __restrict__ Ahi, const __nv_bfloat16* __restrict__ Alo,
    const __nv_bfloat16* __restrict__ Bh,  const __nv_bfloat16* __restrict__ Bl,
    const float* __restrict__ bias,
    __nv_bfloat16* __restrict__ Chi, __nv_bfloat16* __restrict__ Clo,
    float* __restrict__ pooled,
    int K, int kt)
{
    extern __shared__ char smem[];
    const uint32_t sb = smem_u32(smem);
    const int tid = threadIdx.x;
    const int lane = tid & 31;
    const int wid = tid >> 5;
    const int wm = wid & 1;         // 2 m-warps (64 rows each)
    const int wn = wid >> 1;        // 4 n-warps (32 cols each)
    const int bm0 = blockIdx.y * 128;
    const int bn0 = blockIdx.x * 128;

    float* biasS = (float*)(smem + SM_BIAS);
    if (tid < 128) biasS[tid] = bias[bn0 + tid];

    float acc[4][4][4];   // [mfrag][nfrag][reg]
    #pragma unroll
    for (int i = 0; i < 4; i++)
        #pragma unroll
        for (int j = 0; j < 4; j++)
            #pragma unroll
            for (int q = 0; q < 4; q++) acc[i][j][q] = 0.0f;

    // ldmatrix lane address components
    const int g = lane >> 3, li = lane & 7;
    const int a_row_in = (g & 1) * 8 + li;           // + mf*16 + wm*64
    const int a_kseg   = (g >> 1) * 16;              // byte offset within k
    const int b_row_in = (g >> 1) * 8 + li;          // + nb*16 + wn*32
    const int b_kseg   = (g & 1) * 16;

    fill_chunk(sb, 0, 0, Ahi, Alo, Bh, Bl, bm0, bn0, K, tid);
    CP_COMMIT(); CP_WAIT0();
    __syncthreads();

    for (int t = 0; t < kt; t++) {
        const int buf = t & 1;
        if (t + 1 < kt) {
            fill_chunk(sb, buf ^ 1, t + 1, Ahi, Alo, Bh, Bl, bm0, bn0, K, tid);
            CP_COMMIT();
        }
        const uint32_t aHi = ABUF(sb, buf, 0), aLo = ABUF(sb, buf, 1);
        const uint32_t bHi = BBUF(sb, buf, 0), bLo = BBUF(sb, buf, 1);

        #pragma unroll
        for (int ks = 0; ks < 4; ks++) {
            const uint32_t kb = ks * 32;
            uint32_t Ahf[4][4], Alf[4][4], Bhf[2][4], Blf[2][4];
            // A hi frags (4 x m16k16)
            #pragma unroll
            for (int mf = 0; mf < 4; mf++) {
                const int row = wm * 64 + mf * 16 + a_row_in;
                const uint32_t addr = aHi + row * 128 + ((kb + a_kseg) ^ ((row & 7) << 4));
                ldsm4(Ahf[mf][0], Ahf[mf][1], Ahf[mf][2], Ahf[mf][3], addr);
            }
            // B hi frags (2 x k16n16)
            #pragma unroll
            for (int nb = 0; nb < 2; nb++) {
                const int row = wn * 32 + nb * 16 + b_row_in;
                const uint32_t addr = bHi + row * 128 + ((kb + b_kseg) ^ ((row & 7) << 4));
                ldsm4(Bhf[nb][0], Bhf[nb][1], Bhf[nb][2], Bhf[nb][3], addr);
            }
            #pragma unroll
            for (int mf = 0; mf < 4; mf++)
                #pragma unroll
                for (int nf = 0; nf < 4; nf++)
                    mma16816(acc[mf][nf], Ahf[mf][0], Ahf[mf][1], Ahf[mf][2], Ahf[mf][3],
                             Bhf[nf >> 1][(nf & 1) * 2], Bhf[nf >> 1][(nf & 1) * 2 + 1]);
            // B lo
            #pragma unroll
            for (int nb = 0; nb < 2; nb++) {
                const int row = wn * 32 + nb * 16 + b_row_in;
                const uint32_t addr = bLo + row * 128 + ((kb + b_kseg) ^ ((row & 7) << 4));
                ldsm4(Blf[nb][0], Blf[nb][1], Blf[nb][2], Blf[nb][3], addr);
            }
            #pragma unroll
            for (int mf = 0; mf < 4; mf++)
                #pragma unroll
                for (int nf = 0; nf < 4; nf++)
                    mma16816(acc[mf][nf], Ahf[mf][0], Ahf[mf][1], Ahf[mf][2], Ahf[mf][3],
                             Blf[nf >> 1][(nf & 1) * 2], Blf[nf >> 1][(nf & 1) * 2 + 1]);
            // A lo
            #pragma unroll
            for (int mf = 0; mf < 4; mf++) {
                const int row = wm * 64 + mf * 16 + a_row_in;
                const uint32_t addr = aLo + row * 128 + ((kb + a_kseg) ^ ((row & 7) << 4));
                ldsm4(Alf[mf][0], Alf[mf][1], Alf[mf][2], Alf[mf][3], addr);
            }
            #pragma unroll
            for (int mf = 0; mf < 4; mf++)
                #pragma unroll
                for (int nf = 0; nf < 4; nf++)
                    mma16816(acc[mf][nf], Alf[mf][0], Alf[mf][1], Alf[mf][2], Alf[mf][3],
                             Bhf[nf >> 1][(nf & 1) * 2], Bhf[nf >> 1][(nf & 1) * 2 + 1]);
        }
        CP_WAIT0();
        __syncthreads();
    }

    // ---- stage accum tile to smem ----
    float* stg = (float*)smem;   // [128][STG_STRIDE]
    #pragma unroll
    for (int mf = 0; mf < 4; mf++) {
        #pragma unroll
        for (int nf = 0; nf < 4; nf++) {
            const int row = wm * 64 + mf * 16 + (lane >> 2);
            const int col = wn * 32 + nf * 8 + 2 * (lane & 3);
            stg[row * STG_STRIDE + col]           = acc[mf][nf][0];
            stg[row * STG_STRIDE + col + 1]       = acc[mf][nf][1];
            stg[(row + 8) * STG_STRIDE + col]     = acc[mf][nf][2];
            stg[(row + 8) * STG_STRIDE + col + 1] = acc[mf][nf][3];
        }
    }
    __syncthreads();

    if (POOL == 0) {
        const int r = tid >> 1, h = tid & 1;
        uint32_t ph[32], pl[32];
        #pragma unroll
        for (int j = 0; j < 32; j++) {
            const int c0 = h * 64 + 2 * j;
            const float a = fmaxf(stg[r * STG_STRIDE + c0]     + biasS[c0], 0.0f);
            const float b = fmaxf(stg[r * STG_STRIDE + c0 + 1] + biasS[c0 + 1], 0.0f);
            split_pack(a, b, ph[j], pl[j]);
        }
        uint4* dh = (uint4*)(Chi + (size_t)(bm0 + r) * D_H + bn0 + h * 64);
        uint4* dl = (uint4*)(Clo + (size_t)(bm0 + r) * D_H + bn0 + h * 64);
        #pragma unroll
        for (int i = 0; i < 8; i++) {
            dh[i] = make_uint4(ph[4 * i], ph[4 * i + 1], ph[4 * i + 2], ph[4 * i + 3]);
            dl[i] = make_uint4(pl[4 * i], pl[4 * i + 1], pl[4 * i + 2], pl[4 * i + 3]);
        }
    } else {
        float* psum = (float*)(smem + SM_PSUM);   // [2][128]
        float* pmax = (float*)(smem + SM_PMAX);
        const int c = tid >> 1;
        const int h = tid & 1;
        float s = 0.0f, mx = 0.0f;
        const float bb = biasS[c];
        #pragma unroll 4
        for (int r = 0; r < 64; r++) {
            const float v = fmaxf(stg[(h * 64 + r) * STG_STRIDE + c] + bb, 0.0f);
            s += v; mx = fmaxf(mx, v);
        }
        psum[h * 128 + c] = s;
        pmax[h * 128 + c] = mx;
        __syncthreads();
        if (tid < 128) {
            const int b = bm0 >> 9;    // 512 rows per batch element
            const float S = psum[tid] + psum[128 + tid];
            const float M = fmaxf(pmax[tid], pmax[128 + tid]);
            atomicAdd(&pooled[b * (2 * D_H) + bn0 + tid], S);
            atomicMax((int*)&pooled[b * (2 * D_H) + D_H + bn0 + tid], __float_as_int(M));
        }
    }
}

// ---- x elementwise bf16 split ----
__global__ __launch_bounds__(256) void xsplit(const float* __restrict__ x,
                                              __nv_bfloat16* __restrict__ xh,
                                              __nv_bfloat16* __restrict__ xl, int n4)
{
    const int i = blockIdx.x * blockDim.x + threadIdx.x;
    if (i >= n4) return;
    const float4 v = ((const float4*)x)[i];
    uint32_t h0, l0, h1, l1;
    split_pack(v.x, v.y, h0, l0);
    split_pack(v.z, v.w, h1, l1);
    ((uint2*)xh)[i] = make_uint2(h0, h1);
    ((uint2*)xl)[i] = make_uint2(l0, l1);
}

// ---- weight transpose + split: W[K][N] -> Wt{h,l}[N][K] ----
__global__ __launch_bounds__(256) void wconv(const float* __restrict__ W,
                                             __nv_bfloat16* __restrict__ Th,
                                             __nv_bfloat16* __restrict__ Tl,
                                             int K, int N)
{
    __shared__ float s[32][33];
    const int k0 = blockIdx.y * 32, n0 = blockIdx.x * 32;
    const int tx = threadIdx.x, ty = threadIdx.y;   // (32, 8)
    #pragma unroll
    for (int i = 0; i < 4; i++)
        s[ty + 8 * i][tx] = W[(size_t)(k0 + ty + 8 * i) * N + n0 + tx];
    __syncthreads();
    #pragma unroll
    for (int i = 0; i < 4; i++) {
        const int n = ty + 8 * i;
        const float v = s[tx][n];
        __nv_bfloat16 h = __float2bfloat16_rn(v);
        __nv_bfloat16 l = __float2bfloat16_rn(v - __bfloat162float(h));
        Th[(size_t)(n0 + n) * K + k0 + tx] = h;
        Tl[(size_t)(n0 + n) * K + k0 + tx] = l;
    }
}

// ---- rho: split-K fp32 GEMM partials (M=64) ----
// Ws stride 68 floats (272B): float4 row bases stay 16B-aligned.
__global__ __launch_bounds__(256) void rho_splitk(const float* __restrict__ A,
                                                  const float* __restrict__ W,
                                                  float* __restrict__ acc,
                                                  int N, int K, int KS)
{
    __shared__ float As[32][65];
    __shared__ float Ws[32][68];
    const int tid = threadIdx.x;
    const int n0 = blockIdx.x * 64;
    const int k0 = blockIdx.y * KS;
    const int ty = tid >> 4, tx = tid & 15;
    const int m0 = ty * 4, nn0 = tx * 4;

    float c[4][4];
    #pragma unroll
    for (int i = 0; i < 4; i++)
        #pragma unroll
        for (int j = 0; j < 4; j++) c[i][j] = 0.0f;

    for (int kb = 0; kb < KS; kb += 32) {
        {
            const int m = tid >> 2, q = tid & 3;
            const float4* src = (const float4*)(A + (size_t)m * K + k0 + kb + q * 8);
            float4 a0 = src[0], a1 = src[1];
            As[q * 8 + 0][m] = a0.x; As[q * 8 + 1][m] = a0.y;
            As[q * 8 + 2][m] = a0.z; As[q * 8 + 3][m] = a0.w;
            As[q * 8 + 4][m] = a1.x; As[q * 8 + 5][m] = a1.y;
            As[q * 8 + 6][m] = a1.z; As[q * 8 + 7][m] = a1.w;
        }
        {
            const int kk = tid >> 3, seg = tid & 7;
            const float4* src = (const float4*)(W + (size_t)(k0 + kb + kk) * N + n0 + seg * 8);
            float4 w0 = src[0], w1 = src[1];
            *(float4*)&Ws[kk][seg * 8]     = w0;
            *(float4*)&Ws[kk][seg * 8 + 4] = w1;
        }
        __syncthreads();
        #pragma unroll
        for (int kk = 0; kk < 32; kk++) {
            float ra[4], rb[4];
            #pragma unroll
            for (int i = 0; i < 4; i++) ra[i] = As[kk][m0 + i];
            #pragma unroll
            for (int j = 0; j < 4; j++) rb[j] = Ws[kk][nn0 + j];
            #pragma unroll
            for (int i = 0; i < 4; i++)
                #pragma unroll
                for (int j = 0; j < 4; j++)
                    c[i][j] = fmaf(ra[i], rb[j], c[i][j]);
        }
        __syncthreads();
    }
    #pragma unroll
    for (int i = 0; i < 4; i++)
        #pragma unroll
        for (int j = 0; j < 4; j++)
            atomicAdd(&acc[(size_t)(m0 + i) * N + n0 + nn0 + j], c[i][j]);
}

__global__ void bias_relu_k(const float* __restrict__ acc, const float* __restrict__ bias,
                            float* __restrict__ out, int total, int N)
{
    const int i = blockIdx.x * blockDim.x + threadIdx.x;
    if (i < total) out[i] = fmaxf(acc[i] + bias[i & (N - 1)], 0.0f);
}

// zero pooled + racc1 + racc2 in one launch
__global__ void zero_all(float* __restrict__ pooled, float* __restrict__ racc1,
                         float* __restrict__ racc2)
{
    const int i = blockIdx.x * blockDim.x + threadIdx.x;
    if (i < B_SZ * 2 * D_H) pooled[i] = 0.0f;
    if (i < B_SZ * D_H) { racc1[i] = 0.0f; racc2[i] = 0.0f; }
}

extern "C" void kernel_launch(void* const* d_in, const int* in_sizes, int n_in,
                              void* d_out, int out_size)
{
    const float* x      = (const float*)d_in[0];
    const float* W_phi1 = (const float*)d_in[1];
    const float* b_phi1 = (const float*)d_in[2];
    const float* W_phi2 = (const float*)d_in[3];
    const float* b_phi2 = (const float*)d_in[4];
    const float* W_rho1 = (const float*)d_in[5];
    const float* b_rho1 = (const float*)d_in[6];
    const float* W_rho2 = (const float*)d_in[7];
    const float* b_rho2 = (const float*)d_in[8];
    float* out = (float*)d_out;

    __nv_bfloat16 *xh, *xl, *h1h, *h1l, *wt1h, *wt1l, *wt2h, *wt2l;
    float *pooled, *racc1, *r1, *racc2;
    cudaGetSymbolAddress((void**)&xh, g_xh);
    cudaGetSymbolAddress((void**)&xl, g_xl);
    cudaGetSymbolAddress((void**)&h1h, g_h1h);
    cudaGetSymbolAddress((void**)&h1l, g_h1l);
    cudaGetSymbolAddress((void**)&wt1h, g_wt1h);
    cudaGetSymbolAddress((void**)&wt1l, g_wt1l);
    cudaGetSymbolAddress((void**)&wt2h, g_wt2h);
    cudaGetSymbolAddress((void**)&wt2l, g_wt2l);
    cudaGetSymbolAddress((void**)&pooled, g_pooled);
    cudaGetSymbolAddress((void**)&racc1, g_racc1);
    cudaGetSymbolAddress((void**)&r1, g_r1);
    cudaGetSymbolAddress((void**)&racc2, g_racc2);

    cudaFuncSetAttribute(gemm_mma<0>, cudaFuncAttributeMaxDynamicSharedMemorySize, SMEM_DYN);
    cudaFuncSetAttribute(gemm_mma<1>, cudaFuncAttributeMaxDynamicSharedMemorySize, SMEM_DYN);

    zero_all<<<(B_SZ * 2 * D_H + 255) / 256, 256>>>(pooled, racc1, racc2);

    // conversions
    xsplit<<<(M_BIG * D_IN / 4 + 255) / 256, 256>>>(x, xh, xl, M_BIG * D_IN / 4);
    { dim3 g(D_H / 32, D_IN / 32); wconv<<<g, dim3(32, 8)>>>(W_phi1, wt1h, wt1l, D_IN, D_H); }
    { dim3 g(D_H / 32, D_H / 32);  wconv<<<g, dim3(32, 8)>>>(W_phi2, wt2h, wt2l, D_H, D_H); }

    // phi layer 1: [32768,512] @ W1^T -> h1 hi/lo
    {
        dim3 grid(D_H / 128, M_BIG / 128);   // (8, 256)
        gemm_mma<0><<<grid, 256, SMEM_DYN>>>(xh, xl, wt1h, wt1l, b_phi1,
                                             h1h, h1l, nullptr, D_IN, D_IN / 64);
    }
    // phi layer 2 + fused pooling
    {
        dim3 grid(D_H / 128, M_BIG / 128);
        gemm_mma<1><<<grid, 256, SMEM_DYN>>>(h1h, h1l, wt2h, wt2l, b_phi2,
                                             nullptr, nullptr, pooled, D_H, D_H / 64);
    }
    // rho layer 1: [64,2048] @ [2048,1024]
    {
        dim3 grid(D_H / 64, 2 * D_H / 128);  // (16, 16)
        rho_splitk<<<grid, 256>>>(pooled, W_rho1, racc1, D_H, 2 * D_H, 128);
        bias_relu_k<<<(B_SZ * D_H + 255) / 256, 256>>>(racc1, b_rho1, r1, B_SZ * D_H, D_H);
    }
    // rho layer 2: [64,1024] @ [1024,1024] -> out
    {
        dim3 grid(D_H / 64, D_H / 128);      // (16, 8)
        rho_splitk<<<grid, 256>>>(r1, W_rho2, racc2, D_H, D_H, 128);
        bias_relu_k<<<(B_SZ * D_H + 255) / 256, 256>>>(racc2, b_rho2, out, B_SZ * D_H, D_H);
    }
}